// round 16
// baseline (speedup 1.0000x reference)
#include <cuda_runtime.h>
#include <math.h>
#include <stdint.h>

#define N_PTS 32
#define D_DIM 128
#define ITERS 20
#define EPSF  1e-7f
#define CLIPF 1e-7f
#define FULL  0xffffffffu
#define PI_F  3.14159265358979f

__device__ double   g_acc;      // zero-init; last block resets after read
__device__ unsigned g_ticket;   // zero-init; last block resets

__device__ __forceinline__ float warp_sum(float v) {
#pragma unroll
    for (int k = 16; k; k >>= 1) v += __shfl_xor_sync(FULL, v, k);
    return v;
}

// acos via A&S 4.4.46, |err|<=2e-8
__device__ __forceinline__ float acos_poly(float t) {
    float u = fabsf(t);
    float p = fmaf(u, -0.0012624911f, 0.0066700901f);
    p = fmaf(u, p, -0.0170881256f);
    p = fmaf(u, p,  0.0308918810f);
    p = fmaf(u, p, -0.0501743046f);
    p = fmaf(u, p,  0.0889789874f);
    p = fmaf(u, p, -0.2145988016f);
    p = fmaf(u, p,  1.5707963050f);
    float r = sqrtf(1.0f - u) * p;
    return (t >= 0.0f) ? r : (PI_F - r);
}

// warp-level tf32 HMMA: D(16x8,f32) += A(16x8) * B(8x8)
__device__ __forceinline__ void mma_t(float d[4],
                                      uint32_t a0, uint32_t a1, uint32_t a2, uint32_t a3,
                                      uint32_t b0, uint32_t b1) {
    asm volatile(
        "mma.sync.aligned.m16n8k8.row.col.f32.tf32.tf32.f32 "
        "{%0,%1,%2,%3}, {%4,%5,%6,%7}, {%8,%9}, {%0,%1,%2,%3};"
        : "+f"(d[0]), "+f"(d[1]), "+f"(d[2]), "+f"(d[3])
        : "r"(a0), "r"(a1), "r"(a2), "r"(a3), "r"(b0), "r"(b1));
}

// scatter one group's 6 tiles (+ mirrors) into a 32x33 smem Gram
__device__ __forceinline__ void scatter_G(float* Gs, const float d[6][4],
                                          int rr, int c) {
    const int mi[6] = {0, 0, 1, 1, 1, 1};
    const int ni[6] = {0, 1, 0, 1, 2, 3};
#pragma unroll
    for (int t = 0; t < 6; t++) {
        int r0 = 16 * mi[t] + rr, c0 = 8 * ni[t] + 2 * c;
        Gs[33 * r0 + c0]           = d[t][0];
        Gs[33 * r0 + c0 + 1]       = d[t][1];
        Gs[33 * (r0 + 8) + c0]     = d[t][2];
        Gs[33 * (r0 + 8) + c0 + 1] = d[t][3];
    }
#pragma unroll
    for (int t = 2; t < 4; t++) {   // mirror -> rows 0-15, cols 16-31
        int r0 = 16 + rr, c0 = 8 * ni[t] + 2 * c;
        Gs[33 * c0 + r0]           = d[t][0];
        Gs[33 * (c0 + 1) + r0]     = d[t][1];
        Gs[33 * c0 + r0 + 8]       = d[t][2];
        Gs[33 * (c0 + 1) + r0 + 8] = d[t][3];
    }
}

// ==== Fused: 2 groups/warp tf32-HMMA Gram + interleaved Karcher dot-space ====
__global__ __launch_bounds__(32, 16) void karcher_fused(const float* __restrict__ X,
                                                        float* __restrict__ out,
                                                        float invG) {
    __shared__ float Gs0[N_PTS * 33];   // 4224 B each
    __shared__ float Gs1[N_PTS * 33];

    const int lane = threadIdx.x;
    const int rr   = lane >> 2;         // fragment row 0..7
    const int c    = lane & 3;          // fragment k-quad 0..3

    const size_t gbase = (size_t)(2 * blockIdx.x) * (N_PTS * D_DIM);
    const float* __restrict__ b0 = X + gbase + rr * D_DIM + 2 * c;
    const float* __restrict__ b1 = b0 + N_PTS * D_DIM;

    float d0[6][4], d1[6][4];
#pragma unroll
    for (int t = 0; t < 6; t++)
#pragma unroll
        for (int e = 0; e < 4; e++) { d0[t][e] = 0.0f; d1[t][e] = 0.0f; }

#pragma unroll
    for (int s = 0; s < 16; s++) {      // 16 k-steps of 8 cols cover K=128
        const float* q0 = b0 + 8 * s;
        const float* q1 = b1 + 8 * s;
        float2 w0 = __ldg((const float2*)(q0));
        float2 w1 = __ldg((const float2*)(q0 +  8 * D_DIM));
        float2 w2 = __ldg((const float2*)(q0 + 16 * D_DIM));
        float2 w3 = __ldg((const float2*)(q0 + 24 * D_DIM));
        float2 y0 = __ldg((const float2*)(q1));
        float2 y1 = __ldg((const float2*)(q1 +  8 * D_DIM));
        float2 y2 = __ldg((const float2*)(q1 + 16 * D_DIM));
        float2 y3 = __ldg((const float2*)(q1 + 24 * D_DIM));
        uint32_t a00 = __float_as_uint(w0.x), a01 = __float_as_uint(w0.y);
        uint32_t a10 = __float_as_uint(w1.x), a11 = __float_as_uint(w1.y);
        uint32_t a20 = __float_as_uint(w2.x), a21 = __float_as_uint(w2.y);
        uint32_t a30 = __float_as_uint(w3.x), a31 = __float_as_uint(w3.y);
        uint32_t e00 = __float_as_uint(y0.x), e01 = __float_as_uint(y0.y);
        uint32_t e10 = __float_as_uint(y1.x), e11 = __float_as_uint(y1.y);
        uint32_t e20 = __float_as_uint(y2.x), e21 = __float_as_uint(y2.y);
        uint32_t e30 = __float_as_uint(y3.x), e31 = __float_as_uint(y3.y);

        mma_t(d0[0], a00, a10, a01, a11, a00, a01);
        mma_t(d1[0], e00, e10, e01, e11, e00, e01);
        mma_t(d0[1], a00, a10, a01, a11, a10, a11);
        mma_t(d1[1], e00, e10, e01, e11, e10, e11);
        mma_t(d0[2], a20, a30, a21, a31, a00, a01);
        mma_t(d1[2], e20, e30, e21, e31, e00, e01);
        mma_t(d0[3], a20, a30, a21, a31, a10, a11);
        mma_t(d1[3], e20, e30, e21, e31, e10, e11);
        mma_t(d0[4], a20, a30, a21, a31, a20, a21);
        mma_t(d1[4], e20, e30, e21, e31, e20, e21);
        mma_t(d0[5], a20, a30, a21, a31, a30, a31);
        mma_t(d1[5], e20, e30, e21, e31, e30, e31);
    }

    scatter_G(Gs0, d0, rr, c);
    scatter_G(Gs1, d1, rr, c);
    __syncwarp();

    // ---- lane reads its Gram columns, normalize by diag ----
    float gr0[N_PTS], gr1[N_PTS];
#pragma unroll
    for (int m = 0; m < N_PTS; m++) {
        gr0[m] = Gs0[33 * m + lane];
        gr1[m] = Gs1[33 * m + lane];
    }
    float rl0 = rsqrtf(fmaxf(gr0[lane], 1e-24f));
    float rl1 = rsqrtf(fmaxf(gr1[lane], 1e-24f));
#pragma unroll
    for (int m = 0; m < N_PTS; m++) {
        float rm0 = __shfl_sync(FULL, rl0, m);
        float rm1 = __shfl_sync(FULL, rl1, m);
        gr0[m] *= rl0 * rm0;
        gr1[m] *= rl1 * rm1;
    }

    // ---- init dots ----
    float rs0 = 0.0f, rs1 = 0.0f;
#pragma unroll
    for (int m = 0; m < N_PTS; m++) { rs0 += gr0[m]; rs1 += gr1[m]; }
    float t0 = rs0, t1 = rs1;
#pragma unroll
    for (int k = 16; k; k >>= 1) {
        t0 += __shfl_xor_sync(FULL, t0, k);
        t1 += __shfl_xor_sync(FULL, t1, k);
    }
    float dot0 = rs0 * rsqrtf(fmaxf(t0, 1e-24f));
    float dot1 = rs1 * rsqrtf(fmaxf(t1, 1e-24f));

    // ---- 20 interleaved Karcher iterations ----
    const float invN = 1.0f / N_PTS;
#pragma unroll 1
    for (int it = 0; it < ITERS; it++) {
        float u0 = fminf(fmaxf(dot0, -1.0f + CLIPF), 1.0f - CLIPF);
        float u1 = fminf(fmaxf(dot1, -1.0f + CLIPF), 1.0f - CLIPF);
        float th0 = acos_poly(u0), th1 = acos_poly(u1);
        float st0 = sqrtf(fmaf(-u0, u0, 1.0f));
        float st1 = sqrtf(fmaf(-u1, u1, 1.0f));
        float c0v = __fdividef(th0, st0);
        float c1v = __fdividef(th1, st1);

        float g0a = 0.f, g0b = 0.f, g1a = 0.f, g1b = 0.f;
#pragma unroll
        for (int m = 0; m < N_PTS; m += 2) {
            float ca0 = __shfl_sync(FULL, c0v, m);
            float cb0 = __shfl_sync(FULL, c0v, m + 1);
            float ca1 = __shfl_sync(FULL, c1v, m);
            float cb1 = __shfl_sync(FULL, c1v, m + 1);
            g0a = fmaf(gr0[m],     ca0, g0a);
            g0b = fmaf(gr0[m + 1], cb0, g0b);
            g1a = fmaf(gr1[m],     ca1, g1a);
            g1b = fmaf(gr1[m + 1], cb1, g1b);
        }
        float gc0 = g0a + g0b;
        float gc1 = g1a + g1b;

        // quad-interleaved butterfly: s, A2 for both groups
        float pa0 = c0v * dot0, pb0 = c0v * gc0;
        float pa1 = c1v * dot1, pb1 = c1v * gc1;
#pragma unroll
        for (int k = 16; k; k >>= 1) {
            pa0 += __shfl_xor_sync(FULL, pa0, k);
            pb0 += __shfl_xor_sync(FULL, pb0, k);
            pa1 += __shfl_xor_sync(FULL, pa1, k);
            pb1 += __shfl_xor_sync(FULL, pb1, k);
        }

        float vn20 = fmaxf(pb0 - pa0 * pa0, 0.0f) * (invN * invN);
        float vn21 = fmaxf(pb1 - pa1 * pa1, 0.0f) * (invN * invN);
        float vn0 = fmaxf(sqrtf(vn20), EPSF);
        float vn1 = fmaxf(sqrtf(vn21), EPSF);

        float sc0 = __fdividef(__sinf(vn0), vn0);
        float sc1 = __fdividef(__sinf(vn1), vn1);
        float cs0 = __cosf(vn0);
        float cs1 = __cosf(vn1);

        dot0 = fmaf(cs0, dot0, sc0 * invN * fmaf(-pa0, dot0, gc0));
        dot1 = fmaf(cs1, dot1, sc1 * invN * fmaf(-pa1, dot1, gc1));
    }

    // ---- loss: one butterfly for both groups ----
    {
        float u0 = fminf(fmaxf(dot0, -1.0f + CLIPF), 1.0f - CLIPF);
        float u1 = fminf(fmaxf(dot1, -1.0f + CLIPF), 1.0f - CLIPF);
        float th0 = acos_poly(u0), th1 = acos_poly(u1);
        float l = warp_sum(fmaf(th0, th0, th1 * th1));
        if (lane == 0) {
            atomicAdd(&g_acc, (double)l);
            __threadfence();
            unsigned t = atomicAdd(&g_ticket, 1u);
            if (t == gridDim.x - 1) {   // last block: finalize + reset
                out[0] = (float)(g_acc * (double)invG);
                g_acc = 0.0;
                g_ticket = 0u;
            }
        }
    }
}

extern "C" void kernel_launch(void* const* d_in, const int* in_sizes, int n_in,
                              void* d_out, int out_size) {
    const float* X = (const float*)d_in[0];
    const int G = in_sizes[0] / (N_PTS * D_DIM);   // 8000 (even)

    karcher_fused<<<G / 2, 32>>>(X, (float*)d_out, 1.0f / (float)G);
}